// round 3
// baseline (speedup 1.0000x reference)
#include <cuda_runtime.h>

#define S_ 512
#define L_ 256
#define H_ 768
#define P_ 8
#define K_ 8
#define H4_ (H_/4)          // 192
#define SPAN_ (P_*K_)       // 64 entries max per role
#define THREADS_ 192

__global__ __launch_bounds__(THREADS_, 8)
void srl_pool_kernel(const float* __restrict__ emb,
                     const int* __restrict__ idxV,  const int* __restrict__ mV,
                     const int* __restrict__ idxA0, const int* __restrict__ mA0,
                     const int* __restrict__ idxA1, const int* __restrict__ mA1,
                     const int* __restrict__ pred,
                     float* __restrict__ out)
{
    const int s    = blockIdx.x;
    const int role = blockIdx.y;
    const int tid  = threadIdx.x;

    __shared__ int   s_idx[SPAN_ + 8];   // +8 padding slack for round-up
    __shared__ float s_w[SPAN_ + 8];
    __shared__ int   s_n;

    // Pre-zero list (padded slots: idx=0, w=0 -> harmless row-0 load)
    if (tid < SPAN_ + 8) { s_idx[tid] = 0; s_w[tid] = 0.0f; }
    if (tid == 0) s_n = 0;
    __syncthreads();

    // Phase 1: 8 threads, one per predicate p. Fold all gating + divisions
    // into a single per-entry weight; compact non-zero entries.
    if (tid < P_) {
        const int p = tid;
        const int* __restrict__ idx =
            (role == 0) ? idxV : (role == 1) ? idxA0 : idxA1;
        const int* __restrict__ msk =
            (role == 0) ? mV : (role == 1) ? mA0 : mA1;

        const int base = (s * P_ + p) * K_;
        int li[K_], lv[K_];
        int cnt = 0;
        #pragma unroll
        for (int k = 0; k < K_; k++) {
            int ix = idx[base + k];
            int v  = (msk[base + k] != 0) & (ix < L_) & (ix >= 0);
            li[k]  = min(max(ix, 0), L_ - 1);
            lv[k]  = v;
            cnt   += v;
        }

        int npred = 0;
        #pragma unroll
        for (int q = 0; q < P_; q++) npred += (pred[s * P_ + q] != 0);

        float w = 0.0f;
        if ((pred[s * P_ + p] != 0) && cnt > 0 && npred > 0)
            w = 1.0f / ((float)cnt * (float)npred);

        if (w != 0.0f) {
            int pos = atomicAdd(&s_n, cnt);
            #pragma unroll
            for (int k = 0; k < K_; k++) {
                if (lv[k]) {
                    s_idx[pos] = li[k];
                    s_w[pos]   = w;
                    pos++;
                }
            }
        }
    }
    __syncthreads();

    // Phase 2: weighted row-sum; each thread owns one float4 column slice.
    const float4* __restrict__ emb4 =
        reinterpret_cast<const float4*>(emb) + (size_t)s * L_ * H4_;

    float4 acc = make_float4(0.f, 0.f, 0.f, 0.f);

    // Round count up to a multiple of 8 for MLP=8 batched loads.
    const int n = (s_n + 7) & ~7;

    for (int j = 0; j < n; j += 8) {
        int   i0 = s_idx[j+0], i1 = s_idx[j+1], i2 = s_idx[j+2], i3 = s_idx[j+3];
        int   i4 = s_idx[j+4], i5 = s_idx[j+5], i6 = s_idx[j+6], i7 = s_idx[j+7];
        float4 v0 = emb4[i0 * H4_ + tid];
        float4 v1 = emb4[i1 * H4_ + tid];
        float4 v2 = emb4[i2 * H4_ + tid];
        float4 v3 = emb4[i3 * H4_ + tid];
        float4 v4 = emb4[i4 * H4_ + tid];
        float4 v5 = emb4[i5 * H4_ + tid];
        float4 v6 = emb4[i6 * H4_ + tid];
        float4 v7 = emb4[i7 * H4_ + tid];
        float w0 = s_w[j+0], w1 = s_w[j+1], w2 = s_w[j+2], w3 = s_w[j+3];
        float w4 = s_w[j+4], w5 = s_w[j+5], w6 = s_w[j+6], w7 = s_w[j+7];
        acc.x += w0*v0.x; acc.y += w0*v0.y; acc.z += w0*v0.z; acc.w += w0*v0.w;
        acc.x += w1*v1.x; acc.y += w1*v1.y; acc.z += w1*v1.z; acc.w += w1*v1.w;
        acc.x += w2*v2.x; acc.y += w2*v2.y; acc.z += w2*v2.z; acc.w += w2*v2.w;
        acc.x += w3*v3.x; acc.y += w3*v3.y; acc.z += w3*v3.z; acc.w += w3*v3.w;
        acc.x += w4*v4.x; acc.y += w4*v4.y; acc.z += w4*v4.z; acc.w += w4*v4.w;
        acc.x += w5*v5.x; acc.y += w5*v5.y; acc.z += w5*v5.z; acc.w += w5*v5.w;
        acc.x += w6*v6.x; acc.y += w6*v6.y; acc.z += w6*v6.z; acc.w += w6*v6.w;
        acc.x += w7*v7.x; acc.y += w7*v7.y; acc.z += w7*v7.z; acc.w += w7*v7.w;
    }

    // Output: (e_V, e_A0, e_A1) role-major, each (S, H) f32.
    float4* __restrict__ out4 = reinterpret_cast<float4*>(out);
    out4[((size_t)role * S_ + s) * H4_ + tid] = acc;
}

extern "C" void kernel_launch(void* const* d_in, const int* in_sizes, int n_in,
                              void* d_out, int out_size)
{
    const float* emb   = (const float*)d_in[0];
    const int*   idxV  = (const int*)d_in[1];
    const int*   mV    = (const int*)d_in[2];
    const int*   idxA0 = (const int*)d_in[3];
    const int*   mA0   = (const int*)d_in[4];
    const int*   idxA1 = (const int*)d_in[5];
    const int*   mA1   = (const int*)d_in[6];
    const int*   pred  = (const int*)d_in[7];
    float* out = (float*)d_out;

    dim3 grid(S_, 3);
    srl_pool_kernel<<<grid, THREADS_>>>(emb, idxV, mV, idxA0, mA0, idxA1, mA1, pred, out);
}